// round 16
// baseline (speedup 1.0000x reference)
#include <cuda_runtime.h>
#include <cstddef>

// Shapes fixed by the problem
#define Nn 8
#define Cc 128
#define Tt 32
#define HWp 784                         // 28*28
#define TOTAL ((size_t)Nn*Cc*Tt*HWp)    // 25,690,112 floats
#define N4    (TOTAL/4)                 // 6,422,528 float4

// Split: CE memcpy copies the first 75%, SM kernel the last 25%.
#define CE_N4    ((size_t)4816896)      // 0.75 * N4 (float4 units)
#define SM_N4    (N4 - CE_N4)           // 1,605,632
#define BLK      256
#define CP_GRID  1568                   // SM_N4 = CP_GRID*BLK*4 exactly
#define STRD     ((size_t)CP_GRID*BLK)  // 401,408
#define COLD_GRID (Nn*Cc)               // 1024 attention tile blocks
#define GRID     (CP_GRID + COLD_GRID)  // 2592

// ---------------------------------------------------------------------------
// Node 1: cudaMemcpyAsync D2D of the first 75% (copy-engine path, ~7.3 TB/s
//         effective per R13 decomposition).
// Node 2: SM kernel.
//   blocks [0, 1568):    copy blocks — copy the LAST 25% (alpha==0 path);
//                        this real DRAM-bound work absorbs the post-CE
//                        transition/clock-ramp cost that made a bare
//                        trailing guard cost ~7 us (R13/R14).
//   blocks [1568, 2592): attention blocks — alpha==0: exit; alpha!=0:
//                        block nc independently computes the full energy
//                        matrix for its n (redundant recompute -> no grid
//                        barrier, no global scratch), softmaxes, overwrites
//                        its disjoint tile with x + alpha * attn @ x
//                        (serially after the memcpy, so overwrite is safe).
// Writers disjoint for either alpha value -> deterministic, race-free.
// ---------------------------------------------------------------------------
__global__ void __launch_bounds__(BLK, 8) tail_kernel(
        const float* __restrict__ x, const float* __restrict__ alpha,
        float* __restrict__ out) {
    const float a = __ldg(alpha);

    if (blockIdx.x < CP_GRID) {
        if (a != 0.0f) return;         // attention blocks will write out
        const float4* __restrict__ x4 = (const float4*)x;
        float4* __restrict__       o4 = (float4*)out;
        const size_t i = CE_N4 + (size_t)blockIdx.x * BLK + threadIdx.x;
        float4 v0 = __ldcs(x4 + i);
        float4 v1 = __ldcs(x4 + i +     STRD);
        float4 v2 = __ldcs(x4 + i + 2 * STRD);
        float4 v3 = __ldcs(x4 + i + 3 * STRD);
        __stcs(o4 + i,            v0);
        __stcs(o4 + i +     STRD, v1);
        __stcs(o4 + i + 2 * STRD, v2);
        __stcs(o4 + i + 3 * STRD, v3);
        return;
    }

    // ================== attention blocks (cold) ==================
    if (a == 0.0f) return;             // copy paths already wrote out

    const int nc = blockIdx.x - CP_GRID;      // 0..1023
    const int n  = nc >> 7;                   // nc / Cc
    const int tid = threadIdx.x;

    // Overlaid buffer: phase 1 tile(t,j)=buf[t*33+j]; phase 2 attn matrix.
    __shared__ float buf[Tt * 33];            // 4224 B

    // Full energy for this n: E[t][s] = sum_c sum_hw x[n,c,t,hw]*x[n,c,s,hw]
    float acc[4] = {0.f, 0.f, 0.f, 0.f};
    for (int c = 0; c < Cc; c++) {
        const float* __restrict__ A =
            x + ((size_t)n * Cc + c) * (Tt * HWp);
        for (int hw0 = 0; hw0 < HWp; hw0 += 32) {
            for (int e = tid; e < Tt * 32; e += BLK) {
                int t = e >> 5, j = e & 31;
                int hw = hw0 + j;
                buf[t * 33 + j] = (hw < HWp) ? A[t * HWp + hw] : 0.0f;
            }
            __syncthreads();
            #pragma unroll
            for (int k = 0; k < 4; k++) {
                int p = tid + k * BLK;         // (t,s) pair 0..1023
                int t = p >> 5, s = p & 31;
                float v = 0.f;
                #pragma unroll
                for (int j = 0; j < 32; j++)
                    v = fmaf(buf[t * 33 + j], buf[s * 33 + j], v);
                acc[k] += v;
            }
            __syncthreads();
        }
    }
    #pragma unroll
    for (int k = 0; k < 4; k++) {
        int p = tid + k * BLK;
        buf[(p >> 5) * 33 + (p & 31)] = acc[k];
    }
    __syncthreads();

    // Row softmax: 8 warps, rows t = w, w+8, w+16, w+24
    {
        const int lane = tid & 31, w = tid >> 5;
        #pragma unroll
        for (int r = 0; r < 4; r++) {
            int t = w + r * 8;
            float v = buf[t * 33 + lane];
            float m = v;
            #pragma unroll
            for (int o = 16; o > 0; o >>= 1)
                m = fmaxf(m, __shfl_xor_sync(0xffffffffu, m, o));
            float p = __expf(v - m);
            float ssum = p;
            #pragma unroll
            for (int o = 16; o > 0; o >>= 1)
                ssum += __shfl_xor_sync(0xffffffffu, ssum, o);
            buf[t * 33 + lane] = p / ssum;
        }
    }
    __syncthreads();

    // Overwrite this block's tile: out = x + a * attn @ x  (runs after the
    // memcpy node in stream order, so overwriting is safe).
    {
        const float* __restrict__ A = x   + (size_t)nc * (Tt * HWp);
        float* __restrict__       O = out + (size_t)nc * (Tt * HWp);
        for (int hw = tid; hw < HWp; hw += BLK) {
            #pragma unroll 4
            for (int t = 0; t < Tt; t++) {
                float s_acc = 0.f;
                #pragma unroll
                for (int s = 0; s < Tt; s++)
                    s_acc = fmaf(buf[t * 33 + s], A[s * HWp + hw], s_acc);
                O[t * HWp + hw] = fmaf(a, s_acc, A[t * HWp + hw]);
            }
        }
    }
}

// ---------------------------------------------------------------------------
extern "C" void kernel_launch(void* const* d_in, const int* in_sizes, int n_in,
                              void* d_out, int out_size) {
    const float* x     = (const float*)d_in[0];
    const float* alpha = (const float*)d_in[1];
    if (n_in >= 2 && in_sizes[0] == 1) {   // defensive order swap
        x     = (const float*)d_in[1];
        alpha = (const float*)d_in[0];
    }
    float* out = (float*)d_out;

    // Node 1: copy-engine D2D of the first 75% of the tensor.
    cudaMemcpyAsync(out, x, CE_N4 * sizeof(float4),
                    cudaMemcpyDeviceToDevice);

    // Node 2: SM tail copy (last 25%) + in-kernel attention guard.
    tail_kernel<<<GRID, BLK>>>(x, alpha, out);
}

// round 17
// speedup vs baseline: 1.0774x; 1.0774x over previous
#include <cuda_runtime.h>
#include <cstddef>
#include <cstdint>

// Shapes fixed by the problem
#define Nn 8
#define Cc 128
#define Tt 32
#define HWp 784                        // 28*28
#define TOTAL ((size_t)Nn*Cc*Tt*HWp)   // 25,690,112 floats
#define N8    (TOTAL/8)                // 3,211,264 v8 (256-bit) elements

#define BLK       256
#define CP_GRID   6272                 // N8 = CP_GRID*BLK*2 exactly
#define COLD_GRID (Nn*Cc)              // 1024 attention tile blocks
#define GRID      (CP_GRID + COLD_GRID)
#define STRD8     ((size_t)CP_GRID * BLK)   // 1,605,632 (v8 units)

// 256-bit global copy helpers (sm_100+/sm_103a: ld/st.global.v8.f32).
// Halves LSU transactions per byte vs float4 — targets the measured gap
// between SM copy (~4.9 TB/s) and CE (~7.3 TB/s) on identical DRAM.
__device__ __forceinline__ void copy32B_cs(const float* __restrict__ src,
                                           float* __restrict__ dst) {
    float a0, a1, a2, a3, a4, a5, a6, a7;
    asm volatile("ld.global.cs.v8.f32 {%0,%1,%2,%3,%4,%5,%6,%7}, [%8];"
                 : "=f"(a0), "=f"(a1), "=f"(a2), "=f"(a3),
                   "=f"(a4), "=f"(a5), "=f"(a6), "=f"(a7)
                 : "l"(src));
    asm volatile("st.global.cs.v8.f32 [%0], {%1,%2,%3,%4,%5,%6,%7,%8};"
                 :: "l"(dst),
                    "f"(a0), "f"(a1), "f"(a2), "f"(a3),
                    "f"(a4), "f"(a5), "f"(a6), "f"(a7)
                 : "memory");
}

// ---------------------------------------------------------------------------
// ONE kernel, ONE graph node, split grid (proven R10 structure; 35.3 us).
//   blocks [0, 6272):    copy blocks (alpha==0 path): 2 x 256-bit load +
//                        2 x 256-bit store, streaming hints, exit.
//   blocks [6272, 7296): attention blocks (alpha!=0 path): block nc
//                        independently computes the full energy for its n
//                        (redundant recompute -> no barrier, no scratch),
//                        softmax, out = x + alpha * attn @ x on its tile.
// Writers disjoint for either alpha value -> deterministic, race-free.
// ---------------------------------------------------------------------------
__global__ void __launch_bounds__(BLK, 8) fused_kernel(
        const float* __restrict__ x, const float* __restrict__ alpha,
        float* __restrict__ out) {
    const float a = __ldg(alpha);

    if (blockIdx.x < CP_GRID) {
        if (a != 0.0f) return;         // attention blocks will write out
        const size_t i = (size_t)blockIdx.x * BLK + threadIdx.x;
        copy32B_cs(x + i * 8,               out + i * 8);
        copy32B_cs(x + (i + STRD8) * 8,     out + (i + STRD8) * 8);
        return;
    }

    // ================== attention blocks (cold) ==================
    if (a == 0.0f) return;             // copy blocks already wrote out

    const int nc = blockIdx.x - CP_GRID;      // 0..1023
    const int n  = nc >> 7;                   // nc / Cc
    const int tid = threadIdx.x;

    // Overlaid buffer: phase 1 tile(t,j)=buf[t*33+j]; phase 2 attn matrix.
    __shared__ float buf[Tt * 33];            // 4224 B

    // Full energy for this n: E[t][s] = sum_c sum_hw x[n,c,t,hw]*x[n,c,s,hw]
    float acc[4] = {0.f, 0.f, 0.f, 0.f};
    for (int c = 0; c < Cc; c++) {
        const float* __restrict__ A =
            x + ((size_t)n * Cc + c) * (Tt * HWp);
        for (int hw0 = 0; hw0 < HWp; hw0 += 32) {
            for (int e = tid; e < Tt * 32; e += BLK) {
                int t = e >> 5, j = e & 31;
                int hw = hw0 + j;
                buf[t * 33 + j] = (hw < HWp) ? A[t * HWp + hw] : 0.0f;
            }
            __syncthreads();
            #pragma unroll
            for (int k = 0; k < 4; k++) {
                int p = tid + k * BLK;         // (t,s) pair 0..1023
                int t = p >> 5, s = p & 31;
                float v = 0.f;
                #pragma unroll
                for (int j = 0; j < 32; j++)
                    v = fmaf(buf[t * 33 + j], buf[s * 33 + j], v);
                acc[k] += v;
            }
            __syncthreads();
        }
    }
    #pragma unroll
    for (int k = 0; k < 4; k++) {
        int p = tid + k * BLK;
        buf[(p >> 5) * 33 + (p & 31)] = acc[k];
    }
    __syncthreads();

    // Row softmax: 8 warps, rows t = w, w+8, w+16, w+24
    {
        const int lane = tid & 31, w = tid >> 5;
        #pragma unroll
        for (int r = 0; r < 4; r++) {
            int t = w + r * 8;
            float v = buf[t * 33 + lane];
            float m = v;
            #pragma unroll
            for (int o = 16; o > 0; o >>= 1)
                m = fmaxf(m, __shfl_xor_sync(0xffffffffu, m, o));
            float p = __expf(v - m);
            float ssum = p;
            #pragma unroll
            for (int o = 16; o > 0; o >>= 1)
                ssum += __shfl_xor_sync(0xffffffffu, ssum, o);
            buf[t * 33 + lane] = p / ssum;
        }
    }
    __syncthreads();

    // Write this block's tile: out = x + a * attn @ x
    {
        const float* __restrict__ A = x   + (size_t)nc * (Tt * HWp);
        float* __restrict__       O = out + (size_t)nc * (Tt * HWp);
        for (int hw = tid; hw < HWp; hw += BLK) {
            #pragma unroll 4
            for (int t = 0; t < Tt; t++) {
                float s_acc = 0.f;
                #pragma unroll
                for (int s = 0; s < Tt; s++)
                    s_acc = fmaf(buf[t * 33 + s], A[s * HWp + hw], s_acc);
                O[t * HWp + hw] = fmaf(a, s_acc, A[t * HWp + hw]);
            }
        }
    }
}

// ---------------------------------------------------------------------------
extern "C" void kernel_launch(void* const* d_in, const int* in_sizes, int n_in,
                              void* d_out, int out_size) {
    const float* x     = (const float*)d_in[0];
    const float* alpha = (const float*)d_in[1];
    if (n_in >= 2 && in_sizes[0] == 1) {   // defensive order swap
        x     = (const float*)d_in[1];
        alpha = (const float*)d_in[0];
    }
    float* out = (float*)d_out;

    fused_kernel<<<GRID, BLK>>>(x, alpha, out);
}